// round 16
// baseline (speedup 1.0000x reference)
#include <cuda_runtime.h>
#include <cuda_fp16.h>
#include <cstdint>

// BoltzmannRouter (round 15 = R13 fixed): warp-specialized HMMA, spill fix —
// producers load+convert within one iteration (no cross-iteration reg staging).
// x: [16384, 2048] f32, gate_w: [64, 2048] f32, out: [16384, 64] f32

#define D_DIM 2048
#define E_DIM 64
#define BT    128
#define KC    64
#define NC    (D_DIM / KC)     // 32
#define N_ACTIVE 44
#define SC_STRIDE 66

#define ROW_STRIDE 160                  // bytes per smem row (80 halves)
#define A_PLANE (128 * ROW_STRIDE)      // 20480
#define B_PLANE (64 * ROW_STRIDE)       // 10240
#define OFF_B (2 * A_PLANE)             // 40960 (within one buffer)
#define BUF_SIZE (2 * A_PLANE + 2 * B_PLANE)   // 61440
#define SMEM_TOTAL (2 * BUF_SIZE)       // 122880

static __device__ __forceinline__ void mma16816(float* d,
    uint32_t a0, uint32_t a1, uint32_t a2, uint32_t a3, uint32_t b0, uint32_t b1)
{
    asm volatile(
        "mma.sync.aligned.m16n8k16.row.col.f32.f16.f16.f32 "
        "{%0,%1,%2,%3}, {%4,%5,%6,%7}, {%8,%9}, {%0,%1,%2,%3};"
        : "+f"(d[0]), "+f"(d[1]), "+f"(d[2]), "+f"(d[3])
        : "r"(a0), "r"(a1), "r"(a2), "r"(a3), "r"(b0), "r"(b1));
}

// storage column of k' within a 16-k group: [0,1,8,9, 2,3,10,11, 4,5,12,13, 6,7,14,15]
static __device__ __forceinline__ int scol(int kk) {
    return ((kk & 7) >> 1) * 4 + ((kk >> 3) << 1);
}

// exact fp16 2-way split of a float pair; store hi/lo planes
static __device__ __forceinline__ void split_store(
    char* bufbase, int plane_off, int plane, int row, int col_halves, float v0, float v1)
{
    __half2 h = __floats2half2_rn(v0, v1);                 // low=v0, high=v1
    float r0 = v0 - __low2float(h);                        // exact
    float r1 = v1 - __high2float(h);
    __half2 l = __floats2half2_rn(r0, r1);
    char* pp = bufbase + plane_off + row * ROW_STRIDE + col_halves * 2;
    *reinterpret_cast<__half2*>(pp)         = h;
    *reinterpret_cast<__half2*>(pp + plane) = l;
}

__global__ __launch_bounds__(256, 1)
void boltzmann_router_mma(const float* __restrict__ x,
                          const float* __restrict__ w,
                          float* __restrict__ out)
{
    extern __shared__ __align__(16) char sm[];
    const int tid  = threadIdx.x;
    const int lane = tid & 31;
    const int warp = tid >> 5;            // 8 warps: 0-3 consumers, 4-7 producers
    const int tok0 = blockIdx.x * BT;
    const bool consumer = warp < 4;

    // ---- consumer mapping: warp = 32 tokens x 64 experts ----
    const int tm = warp * 32;             // (only meaningful for consumers)
    const int g = lane >> 2, t = lane & 3;
    float d[2][8][4];
    #pragma unroll
    for (int m = 0; m < 2; m++)
        #pragma unroll
        for (int n = 0; n < 8; n++)
            #pragma unroll
            for (int q = 0; q < 4; q++) d[m][n][q] = 0.0f;

    // ---- producer coords (warps 4-7; 128 threads) ----
    const int ptid = tid & 127;
    const int lrow = ptid >> 4;           // 0..7
    const int lcol = ptid & 15;           // 16B piece within 64-float chunk row
    const float* xp = x + (size_t)(tok0 + lrow) * D_DIM + lcol * 4;
    const float* wp = w + (size_t)lrow * D_DIM + lcol * 4;
    const int kl = lcol * 4;
    const int c0 = ((kl >> 4) << 4) + scol(kl & 15);
    const int c2 = (((kl + 2) >> 4) << 4) + scol((kl + 2) & 15);

    // load + convert chunk cc into buffer `buf` (all registers scope-local)
    auto produce = [&](int cc, int buf) {
        char* bb = sm + buf * BUF_SIZE;
        #pragma unroll
        for (int jb = 0; jb < 2; jb++) {
            float4 v[8];
            #pragma unroll
            for (int j = 0; j < 8; j++)
                v[j] = *reinterpret_cast<const float4*>(
                           xp + cc * KC + (size_t)(jb * 8 + j) * 8 * D_DIM);
            #pragma unroll
            for (int j = 0; j < 8; j++) {
                int row = lrow + 8 * (jb * 8 + j);
                split_store(bb, 0, A_PLANE, row, c0, v[j].x, v[j].y);
                split_store(bb, 0, A_PLANE, row, c2, v[j].z, v[j].w);
            }
        }
        {
            float4 v[8];
            #pragma unroll
            for (int j = 0; j < 8; j++)
                v[j] = *reinterpret_cast<const float4*>(
                           wp + cc * KC + (size_t)j * 8 * D_DIM);
            #pragma unroll
            for (int j = 0; j < 8; j++) {
                int row = lrow + 8 * j;
                split_store(bb, OFF_B, B_PLANE, row, c0, v[j].x, v[j].y);
                split_store(bb, OFF_B, B_PLANE, row, c2, v[j].z, v[j].w);
            }
        }
    };

    // ---- prologue: producers fill buf0 with chunk0 ----
    if (!consumer)
        produce(0, 0);
    __syncthreads();

    for (int c = 0; c < NC; c++) {
        if (consumer) {
            // ---- MMA on chunk c from buf c&1 ----
            const char* bb = sm + (c & 1) * BUF_SIZE;
            #pragma unroll
            for (int ks = 0; ks < 4; ks++) {
                const int kcol = (ks * 16 + 4 * t) * 2;
                // A fragments: af[m][p] = {a0,a1,a2,a3}, p = split (hi/lo)
                uint4 af[2][2];
                #pragma unroll
                for (int m = 0; m < 2; m++)
                    #pragma unroll
                    for (int p = 0; p < 2; p++) {
                        const char* pa = bb + p * A_PLANE
                                       + (tm + m * 16 + g) * ROW_STRIDE + kcol;
                        uint2 lo = *reinterpret_cast<const uint2*>(pa);
                        uint2 hi = *reinterpret_cast<const uint2*>(pa + 8 * ROW_STRIDE);
                        af[m][p] = make_uint4(lo.x, hi.x, lo.y, hi.y);
                    }
                // B fragments for all 8 n-tiles, both splits
                uint2 bh[8], bl[8];
                #pragma unroll
                for (int n = 0; n < 8; n++) {
                    const char* pb = bb + OFF_B + (n * 8 + g) * ROW_STRIDE + kcol;
                    bh[n] = *reinterpret_cast<const uint2*>(pb);
                    bl[n] = *reinterpret_cast<const uint2*>(pb + B_PLANE);
                }
                // split-product OUTER loop: per accumulator the order is still
                // hh, hl, lh, ll (bit-identical); consecutive issues hit 16
                // different accumulators => no RAW stalls.
                #pragma unroll
                for (int n = 0; n < 8; n++)     // q0: a-hi x b-hi
                    #pragma unroll
                    for (int m = 0; m < 2; m++)
                        mma16816(d[m][n], af[m][0].x, af[m][0].y, af[m][0].z, af[m][0].w,
                                 bh[n].x, bh[n].y);
                #pragma unroll
                for (int n = 0; n < 8; n++)     // q1: a-hi x b-lo
                    #pragma unroll
                    for (int m = 0; m < 2; m++)
                        mma16816(d[m][n], af[m][0].x, af[m][0].y, af[m][0].z, af[m][0].w,
                                 bl[n].x, bl[n].y);
                #pragma unroll
                for (int n = 0; n < 8; n++)     // q2: a-lo x b-hi
                    #pragma unroll
                    for (int m = 0; m < 2; m++)
                        mma16816(d[m][n], af[m][1].x, af[m][1].y, af[m][1].z, af[m][1].w,
                                 bh[n].x, bh[n].y);
                #pragma unroll
                for (int n = 0; n < 8; n++)     // q3: a-lo x b-lo
                    #pragma unroll
                    for (int m = 0; m < 2; m++)
                        mma16816(d[m][n], af[m][1].x, af[m][1].y, af[m][1].z, af[m][1].w,
                                 bl[n].x, bl[n].y);
            }
        } else {
            // ---- producers: load+convert chunk c+1 into the other buffer ----
            if (c + 1 < NC)
                produce(c + 1, (c + 1) & 1);
        }
        __syncthreads();
    }

    // ---- consumers write scaled scores (into buffer-0 region) ----
    float* sc = reinterpret_cast<float*>(sm);
    const float INV_TEMP = 0.36787944117144233f;  // 1/e
    if (consumer) {
        #pragma unroll
        for (int m = 0; m < 2; m++) {
            int r0 = tm + m * 16 + g, r1 = r0 + 8;
            #pragma unroll
            for (int n = 0; n < 8; n++) {
                int cb = n * 8 + 2 * t;
                sc[r0 * SC_STRIDE + cb]     = d[m][n][0] * INV_TEMP;
                sc[r0 * SC_STRIDE + cb + 1] = d[m][n][1] * INV_TEMP;
                sc[r1 * SC_STRIDE + cb]     = d[m][n][2] * INV_TEMP;
                sc[r1 * SC_STRIDE + cb + 1] = d[m][n][3] * INV_TEMP;
            }
        }
    }
    __syncthreads();

    // ---- epilogue: all 8 warps, one warp per 16 tokens ----
    for (int tt = 0; tt < 16; tt++) {
        int tk = warp * 16 + tt;
        float s0 = sc[tk * SC_STRIDE + lane];
        float s1 = sc[tk * SC_STRIDE + 32 + lane];

        float mx = fmaxf(s0, s1);
        #pragma unroll
        for (int o = 16; o > 0; o >>= 1)
            mx = fmaxf(mx, __shfl_xor_sync(0xFFFFFFFFu, mx, o));

        float e0v = __expf(s0 - mx);
        float e1v = __expf(s1 - mx);
        float z = e0v + e1v;
        #pragma unroll
        for (int o = 16; o > 0; o >>= 1)
            z += __shfl_xor_sync(0xFFFFFFFFu, z, o);

        // rank = #{j : s_j > s_i, ties broken by lower index}
        int cc0 = 0, cc1 = 0;
        #pragma unroll 16
        for (int j = 0; j < E_DIM; j++) {
            float sj = sc[tk * SC_STRIDE + j];
            cc0 += (sj > s0) || (sj == s0 && j < lane);
            cc1 += (sj > s1) || (sj == s1 && j < lane + 32);
        }
        bool keep0 = cc0 < N_ACTIVE;
        bool keep1 = cc1 < N_ACTIVE;

        float sk = (keep0 ? e0v : 0.0f) + (keep1 ? e1v : 0.0f);
        #pragma unroll
        for (int o = 16; o > 0; o >>= 1)
            sk += __shfl_xor_sync(0xFFFFFFFFu, sk, o);

        float inv = 1.0f / (sk + 1e-8f * z);
        size_t base = (size_t)(tok0 + tk) * E_DIM;
        out[base + lane]      = keep0 ? e0v * inv : 0.0f;
        out[base + lane + 32] = keep1 ? e1v * inv : 0.0f;
    }
}

extern "C" void kernel_launch(void* const* d_in, const int* in_sizes, int n_in,
                              void* d_out, int out_size)
{
    const float* x = (const float*)d_in[0];   // [N, 2048]
    const float* w = (const float*)d_in[1];   // [64, 2048]
    float* out     = (float*)d_out;           // [N, 64]
    int ntok = in_sizes[0] / D_DIM;           // 16384

    cudaFuncSetAttribute(boltzmann_router_mma,
                         cudaFuncAttributeMaxDynamicSharedMemorySize, SMEM_TOTAL);
    boltzmann_router_mma<<<ntok / BT, 256, SMEM_TOTAL>>>(x, w, out);
}

// round 17
// speedup vs baseline: 1.1700x; 1.1700x over previous
#include <cuda_runtime.h>
#include <cuda_fp16.h>
#include <cstdint>

// BoltzmannRouter (round 16): BT=64, 2 CTAs/SM (occ 25%) warp-specialized HMMA.
// x: [16384, 2048] f32, gate_w: [64, 2048] f32, out: [16384, 64] f32

#define D_DIM 2048
#define E_DIM 64
#define BT    64
#define KC    64
#define NC    (D_DIM / KC)     // 32
#define N_ACTIVE 44
#define SC_STRIDE 66

#define ROW_STRIDE 160                  // bytes per smem row (80 halves)
#define A_PLANE (64 * ROW_STRIDE)       // 10240
#define B_PLANE (64 * ROW_STRIDE)       // 10240
#define OFF_B (2 * A_PLANE)             // 20480 (within one buffer)
#define BUF_SIZE (2 * A_PLANE + 2 * B_PLANE)   // 40960
#define SMEM_TOTAL (2 * BUF_SIZE)       // 81920

static __device__ __forceinline__ void mma16816(float* d,
    uint32_t a0, uint32_t a1, uint32_t a2, uint32_t a3, uint32_t b0, uint32_t b1)
{
    asm volatile(
        "mma.sync.aligned.m16n8k16.row.col.f32.f16.f16.f32 "
        "{%0,%1,%2,%3}, {%4,%5,%6,%7}, {%8,%9}, {%0,%1,%2,%3};"
        : "+f"(d[0]), "+f"(d[1]), "+f"(d[2]), "+f"(d[3])
        : "r"(a0), "r"(a1), "r"(a2), "r"(a3), "r"(b0), "r"(b1));
}

// storage column of k' within a 16-k group: [0,1,8,9, 2,3,10,11, 4,5,12,13, 6,7,14,15]
static __device__ __forceinline__ int scol(int kk) {
    return ((kk & 7) >> 1) * 4 + ((kk >> 3) << 1);
}

// exact fp16 2-way split of a float pair; store hi/lo planes
static __device__ __forceinline__ void split_store(
    char* bufbase, int plane_off, int plane, int row, int col_halves, float v0, float v1)
{
    __half2 h = __floats2half2_rn(v0, v1);                 // low=v0, high=v1
    float r0 = v0 - __low2float(h);                        // exact
    float r1 = v1 - __high2float(h);
    __half2 l = __floats2half2_rn(r0, r1);
    char* pp = bufbase + plane_off + row * ROW_STRIDE + col_halves * 2;
    *reinterpret_cast<__half2*>(pp)         = h;
    *reinterpret_cast<__half2*>(pp + plane) = l;
}

__global__ __launch_bounds__(256, 2)
void boltzmann_router_mma(const float* __restrict__ x,
                          const float* __restrict__ w,
                          float* __restrict__ out)
{
    extern __shared__ __align__(16) char sm[];
    const int tid  = threadIdx.x;
    const int lane = tid & 31;
    const int warp = tid >> 5;            // 8 warps: 0-3 consumers, 4-7 producers
    const int tok0 = blockIdx.x * BT;
    const bool consumer = warp < 4;

    // ---- consumer mapping: warp = 16 tokens x 64 experts ----
    const int tm = warp * 16;             // (only meaningful for consumers)
    const int g = lane >> 2, t = lane & 3;
    float d[8][4];
    #pragma unroll
    for (int n = 0; n < 8; n++)
        #pragma unroll
        for (int q = 0; q < 4; q++) d[n][q] = 0.0f;

    // ---- producer coords (warps 4-7; 128 threads) ----
    const int ptid = tid & 127;
    const int lrow = ptid >> 4;           // 0..7
    const int lcol = ptid & 15;           // 16B piece within 64-float chunk row
    const float* xp = x + (size_t)(tok0 + lrow) * D_DIM + lcol * 4;
    const float* wp = w + (size_t)lrow * D_DIM + lcol * 4;
    const int kl = lcol * 4;
    const int c0 = ((kl >> 4) << 4) + scol(kl & 15);
    const int c2 = (((kl + 2) >> 4) << 4) + scol((kl + 2) & 15);

    // load + convert chunk cc into buffer `buf` (all registers scope-local)
    auto produce = [&](int cc, int buf) {
        char* bb = sm + buf * BUF_SIZE;
        {
            float4 v[8];
            #pragma unroll
            for (int j = 0; j < 8; j++)
                v[j] = *reinterpret_cast<const float4*>(
                           xp + cc * KC + (size_t)j * 8 * D_DIM);
            #pragma unroll
            for (int j = 0; j < 8; j++) {
                int row = lrow + 8 * j;
                split_store(bb, 0, A_PLANE, row, c0, v[j].x, v[j].y);
                split_store(bb, 0, A_PLANE, row, c2, v[j].z, v[j].w);
            }
        }
        {
            float4 v[8];
            #pragma unroll
            for (int j = 0; j < 8; j++)
                v[j] = *reinterpret_cast<const float4*>(
                           wp + cc * KC + (size_t)j * 8 * D_DIM);
            #pragma unroll
            for (int j = 0; j < 8; j++) {
                int row = lrow + 8 * j;
                split_store(bb, OFF_B, B_PLANE, row, c0, v[j].x, v[j].y);
                split_store(bb, OFF_B, B_PLANE, row, c2, v[j].z, v[j].w);
            }
        }
    };

    // ---- prologue: producers fill buf0 with chunk0 ----
    if (!consumer)
        produce(0, 0);
    __syncthreads();

    for (int c = 0; c < NC; c++) {
        if (consumer) {
            // ---- MMA on chunk c from buf c&1 ----
            const char* bb = sm + (c & 1) * BUF_SIZE;
            #pragma unroll
            for (int ks = 0; ks < 4; ks++) {
                const int kcol = (ks * 16 + 4 * t) * 2;
                // A fragments: af[p] = {a0,a1,a2,a3}, p = split (hi/lo)
                uint4 af[2];
                #pragma unroll
                for (int p = 0; p < 2; p++) {
                    const char* pa = bb + p * A_PLANE
                                   + (tm + g) * ROW_STRIDE + kcol;
                    uint2 lo = *reinterpret_cast<const uint2*>(pa);
                    uint2 hi = *reinterpret_cast<const uint2*>(pa + 8 * ROW_STRIDE);
                    af[p] = make_uint4(lo.x, hi.x, lo.y, hi.y);
                }
                // B fragments for all 8 n-tiles, both splits
                uint2 bh[8], bl[8];
                #pragma unroll
                for (int n = 0; n < 8; n++) {
                    const char* pb = bb + OFF_B + (n * 8 + g) * ROW_STRIDE + kcol;
                    bh[n] = *reinterpret_cast<const uint2*>(pb);
                    bl[n] = *reinterpret_cast<const uint2*>(pb + B_PLANE);
                }
                // split-product OUTER loop: per accumulator the order is still
                // hh, hl, lh, ll (bit-identical); consecutive issues hit 8
                // different accumulators => no RAW stalls.
                #pragma unroll
                for (int n = 0; n < 8; n++)     // q0: a-hi x b-hi
                    mma16816(d[n], af[0].x, af[0].y, af[0].z, af[0].w, bh[n].x, bh[n].y);
                #pragma unroll
                for (int n = 0; n < 8; n++)     // q1: a-hi x b-lo
                    mma16816(d[n], af[0].x, af[0].y, af[0].z, af[0].w, bl[n].x, bl[n].y);
                #pragma unroll
                for (int n = 0; n < 8; n++)     // q2: a-lo x b-hi
                    mma16816(d[n], af[1].x, af[1].y, af[1].z, af[1].w, bh[n].x, bh[n].y);
                #pragma unroll
                for (int n = 0; n < 8; n++)     // q3: a-lo x b-lo
                    mma16816(d[n], af[1].x, af[1].y, af[1].z, af[1].w, bl[n].x, bl[n].y);
            }
        } else {
            // ---- producers: load+convert chunk c+1 into the other buffer ----
            if (c + 1 < NC)
                produce(c + 1, (c + 1) & 1);
        }
        __syncthreads();
    }

    // ---- consumers write scaled scores (into buffer-0 region) ----
    float* sc = reinterpret_cast<float*>(sm);
    const float INV_TEMP = 0.36787944117144233f;  // 1/e
    if (consumer) {
        int r0 = tm + g, r1 = r0 + 8;
        #pragma unroll
        for (int n = 0; n < 8; n++) {
            int cb = n * 8 + 2 * t;
            sc[r0 * SC_STRIDE + cb]     = d[n][0] * INV_TEMP;
            sc[r0 * SC_STRIDE + cb + 1] = d[n][1] * INV_TEMP;
            sc[r1 * SC_STRIDE + cb]     = d[n][2] * INV_TEMP;
            sc[r1 * SC_STRIDE + cb + 1] = d[n][3] * INV_TEMP;
        }
    }
    __syncthreads();

    // ---- epilogue: all 8 warps, one warp per 8 tokens ----
    for (int tt = 0; tt < 8; tt++) {
        int tk = warp * 8 + tt;
        float s0 = sc[tk * SC_STRIDE + lane];
        float s1 = sc[tk * SC_STRIDE + 32 + lane];

        float mx = fmaxf(s0, s1);
        #pragma unroll
        for (int o = 16; o > 0; o >>= 1)
            mx = fmaxf(mx, __shfl_xor_sync(0xFFFFFFFFu, mx, o));

        float e0v = __expf(s0 - mx);
        float e1v = __expf(s1 - mx);
        float z = e0v + e1v;
        #pragma unroll
        for (int o = 16; o > 0; o >>= 1)
            z += __shfl_xor_sync(0xFFFFFFFFu, z, o);

        // rank = #{j : s_j > s_i, ties broken by lower index}
        int cc0 = 0, cc1 = 0;
        #pragma unroll 16
        for (int j = 0; j < E_DIM; j++) {
            float sj = sc[tk * SC_STRIDE + j];
            cc0 += (sj > s0) || (sj == s0 && j < lane);
            cc1 += (sj > s1) || (sj == s1 && j < lane + 32);
        }
        bool keep0 = cc0 < N_ACTIVE;
        bool keep1 = cc1 < N_ACTIVE;

        float sk = (keep0 ? e0v : 0.0f) + (keep1 ? e1v : 0.0f);
        #pragma unroll
        for (int o = 16; o > 0; o >>= 1)
            sk += __shfl_xor_sync(0xFFFFFFFFu, sk, o);

        float inv = 1.0f / (sk + 1e-8f * z);
        size_t base = (size_t)(tok0 + tk) * E_DIM;
        out[base + lane]      = keep0 ? e0v * inv : 0.0f;
        out[base + lane + 32] = keep1 ? e1v * inv : 0.0f;
    }
}

extern "C" void kernel_launch(void* const* d_in, const int* in_sizes, int n_in,
                              void* d_out, int out_size)
{
    const float* x = (const float*)d_in[0];   // [N, 2048]
    const float* w = (const float*)d_in[1];   // [64, 2048]
    float* out     = (float*)d_out;           // [N, 64]
    int ntok = in_sizes[0] / D_DIM;           // 16384

    cudaFuncSetAttribute(boltzmann_router_mma,
                         cudaFuncAttributeMaxDynamicSharedMemorySize, SMEM_TOTAL);
    boltzmann_router_mma<<<ntok / BT, 256, SMEM_TOTAL>>>(x, w, out);
}